// round 10
// baseline (speedup 1.0000x reference)
#include <cuda_runtime.h>
#include <cuda_bf16.h>

#define N_NODES  100000
#define N_EDGES  1200000
#define N_GRAPHS 256
#define SCAN_BLOCKS 98   // ceil(100000/1024)

// ---------------- device scratch (no allocs allowed) ----------------
__device__ int   g_deg[N_NODES];
__device__ int   g_rowptr[N_NODES + 1];
__device__ int   g_cur[N_NODES];
__device__ int   g_csr[N_EDGES];
__device__ int   g_bsums[SCAN_BLOCKS];
__device__ int   g_boff[SCAN_BLOCKS];
__device__ __align__(16) float g_h1[N_NODES * 64];
__device__ __align__(16) float g_h2[N_NODES * 64];
__device__ __align__(16) float g_pool[N_GRAPHS * 64];

// ---------------- packed f32x2 helpers ----------------
__device__ __forceinline__ unsigned long long pack2(float x, float y) {
    unsigned long long r;
    asm("mov.b64 %0, {%1, %2};" : "=l"(r) : "f"(x), "f"(y));
    return r;
}
__device__ __forceinline__ float2 unpack2(unsigned long long v) {
    float2 r;
    asm("mov.b64 {%0, %1}, %2;" : "=f"(r.x), "=f"(r.y) : "l"(v));
    return r;
}
__device__ __forceinline__ void fma2(unsigned long long& d,
                                     unsigned long long a,
                                     unsigned long long b) {
    asm("fma.rn.f32x2 %0, %1, %2, %0;" : "+l"(d) : "l"(a), "l"(b));
}

// ---------------- CSR build ----------------
__global__ void zero_kernel() {
    int i = blockIdx.x * blockDim.x + threadIdx.x;
    if (i < N_NODES) g_deg[i] = 0;
    if (i < N_GRAPHS * 64) g_pool[i] = 0.0f;
}

__global__ void count_kernel(const int* __restrict__ edge) {
    int e = blockIdx.x * blockDim.x + threadIdx.x;
    if (e < N_EDGES) {
        int dst = edge[N_EDGES + e];
        atomicAdd(&g_deg[dst], 1);
    }
}

__global__ void scan_blocks_kernel() {
    __shared__ int s[1024];
    int tid = threadIdx.x;
    int i = blockIdx.x * 1024 + tid;
    int v = (i < N_NODES) ? g_deg[i] : 0;
    s[tid] = v;
    __syncthreads();
    for (int off = 1; off < 1024; off <<= 1) {
        int t = (tid >= off) ? s[tid - off] : 0;
        __syncthreads();
        s[tid] += t;
        __syncthreads();
    }
    if (i < N_NODES) g_rowptr[i] = s[tid] - v;  // exclusive
    if (tid == 1023) g_bsums[blockIdx.x] = s[1023];
}

__global__ void scan_top_kernel() {
    __shared__ int s[128];
    int tid = threadIdx.x;
    int v = (tid < SCAN_BLOCKS) ? g_bsums[tid] : 0;
    s[tid] = v;
    __syncthreads();
    for (int off = 1; off < 128; off <<= 1) {
        int t = (tid >= off) ? s[tid - off] : 0;
        __syncthreads();
        s[tid] += t;
        __syncthreads();
    }
    if (tid < SCAN_BLOCKS) g_boff[tid] = s[tid] - v;  // exclusive
}

__global__ void scan_add_kernel() {
    int i = blockIdx.x * 1024 + threadIdx.x;
    if (i < N_NODES) {
        int r = g_rowptr[i] + g_boff[blockIdx.x];
        g_rowptr[i] = r;
        g_cur[i] = r;
    }
    if (i == 0) g_rowptr[N_NODES] = N_EDGES;
}

__global__ void fill_kernel(const int* __restrict__ edge) {
    int e = blockIdx.x * blockDim.x + threadIdx.x;
    if (e < N_EDGES) {
        int src = edge[e];
        int dst = edge[N_EDGES + e];
        int pos = atomicAdd(&g_cur[dst], 1);
        g_csr[pos] = src;
    }
}

// ---------------- layer 1: x[100k,8] -> g_h1[100k,64], relu ----------------
__global__ void sage8_kernel(const float* __restrict__ x,
                             const float* __restrict__ Wl,
                             const float* __restrict__ bias,
                             const float* __restrict__ Wr) {
    __shared__ float sA[128 * 17];   // [node][16] mean(0..7) | self(8..15), pad
    __shared__ float sB[16 * 64];    // rows 0..7 = Wl, 8..15 = Wr
    __shared__ float sBias[64];

    const int tid = threadIdx.x;
    if (tid < 128) ((float4*)sB)[tid] = ((const float4*)Wl)[tid];
    else           ((float4*)sB)[tid] = ((const float4*)Wr)[tid - 128];
    if (tid < 64) sBias[tid] = bias[tid];

    const int base = blockIdx.x * 128;
    const float4* x4 = (const float4*)x;

    if (tid < 128) {
        int node = base + tid;
        float4 a0 = make_float4(0, 0, 0, 0), a1 = make_float4(0, 0, 0, 0);
        float4 b0 = make_float4(0, 0, 0, 0), b1 = make_float4(0, 0, 0, 0);
        float4 s0 = make_float4(0, 0, 0, 0), s1 = make_float4(0, 0, 0, 0);
        if (node < N_NODES) {
            int start = g_rowptr[node], end = g_rowptr[node + 1];
            int e = start;
            for (; e + 1 < end; e += 2) {
                int sa = g_csr[e], sb = g_csr[e + 1];
                float4 u0 = x4[sa * 2], u1 = x4[sa * 2 + 1];
                float4 w0 = x4[sb * 2], w1 = x4[sb * 2 + 1];
                a0.x += u0.x; a0.y += u0.y; a0.z += u0.z; a0.w += u0.w;
                a1.x += u1.x; a1.y += u1.y; a1.z += u1.z; a1.w += u1.w;
                b0.x += w0.x; b0.y += w0.y; b0.z += w0.z; b0.w += w0.w;
                b1.x += w1.x; b1.y += w1.y; b1.z += w1.z; b1.w += w1.w;
            }
            if (e < end) {
                int sa = g_csr[e];
                float4 u0 = x4[sa * 2], u1 = x4[sa * 2 + 1];
                a0.x += u0.x; a0.y += u0.y; a0.z += u0.z; a0.w += u0.w;
                a1.x += u1.x; a1.y += u1.y; a1.z += u1.z; a1.w += u1.w;
            }
            float inv = 1.0f / (float)max(end - start, 1);
            a0.x = (a0.x + b0.x) * inv; a0.y = (a0.y + b0.y) * inv;
            a0.z = (a0.z + b0.z) * inv; a0.w = (a0.w + b0.w) * inv;
            a1.x = (a1.x + b1.x) * inv; a1.y = (a1.y + b1.y) * inv;
            a1.z = (a1.z + b1.z) * inv; a1.w = (a1.w + b1.w) * inv;
            s0 = x4[node * 2]; s1 = x4[node * 2 + 1];
        }
        float* row = sA + tid * 17;
        row[0] = a0.x; row[1] = a0.y; row[2] = a0.z; row[3] = a0.w;
        row[4] = a1.x; row[5] = a1.y; row[6] = a1.z; row[7] = a1.w;
        row[8] = s0.x; row[9] = s0.y; row[10] = s0.z; row[11] = s0.w;
        row[12] = s1.x; row[13] = s1.y; row[14] = s1.z; row[15] = s1.w;
    }
    __syncthreads();

    const int tn = tid & 15, tm = tid >> 4;
    float acc[8][4];
#pragma unroll
    for (int i = 0; i < 8; ++i)
#pragma unroll
        for (int j = 0; j < 4; ++j) acc[i][j] = sBias[tn * 4 + j];

#pragma unroll
    for (int k = 0; k < 16; ++k) {
        float4 bv = *(const float4*)&sB[k * 64 + tn * 4];
        float a[8];
#pragma unroll
        for (int i = 0; i < 8; ++i) a[i] = sA[(tm * 8 + i) * 17 + k];
#pragma unroll
        for (int i = 0; i < 8; ++i) {
            acc[i][0] += a[i] * bv.x;
            acc[i][1] += a[i] * bv.y;
            acc[i][2] += a[i] * bv.z;
            acc[i][3] += a[i] * bv.w;
        }
    }

    float4* hout4 = (float4*)g_h1;
#pragma unroll
    for (int i = 0; i < 8; ++i) {
        int node = base + tm * 8 + i;
        if (node < N_NODES) {
            float4 o;
            o.x = fmaxf(acc[i][0], 0.0f);
            o.y = fmaxf(acc[i][1], 0.0f);
            o.z = fmaxf(acc[i][2], 0.0f);
            o.w = fmaxf(acc[i][3], 0.0f);
            hout4[node * 16 + tn] = o;
        }
    }
}

// ---------------- layers 2/3: h[100k,64] -> h'[100k,64] ----------------
// Warp-autonomous, FFMA2 with k-pair accumulators (acc = {even-k, odd-k} sums).
// Tile 96 nodes, 256 threads, warp owns 12 rows. Weights TRANSPOSED in smem
// (sBT[n][k], stride 66) so b = {B[k][n],B[k+1][n]} is one LDS.64, conflict-
// free across lanes (bank = 2*tn). A loads unchanged (row-major, broadcast).
#define TILE_N64 96
#define A_STRIDE 68   // row-major A rows, 16B-aligned
#define BT_STRIDE 66  // transposed weight rows (even => LDS.64 aligned)
#define SM64_BYTES ((TILE_N64 * A_STRIDE + 2 * 64 * BT_STRIDE) * 4)  // 59904

__global__ void __launch_bounds__(256, 3) sage64_kernel(
                              int srcbuf,
                              const float* __restrict__ Wl,
                              const float* __restrict__ bias,
                              const float* __restrict__ Wr,
                              int do_relu) {
    extern __shared__ float sm64[];
    float* sA  = sm64;                              // [96][68]
    float* sBl = sm64 + TILE_N64 * A_STRIDE;        // [64][66] transposed
    float* sBr = sBl + 64 * BT_STRIDE;              // [64][66] transposed

    const float* hin = (srcbuf == 0) ? g_h1 : g_h2;
    float* hout      = (srcbuf == 0) ? g_h2 : g_h1;

    const int tid  = threadIdx.x;
    const int base = blockIdx.x * TILE_N64;
    const int warp = tid >> 5, lane = tid & 31;
    const int half = lane >> 4, hl = lane & 15;
    const int tn = tid & 15, tm = tid >> 4;

    // ---- weights transposed into smem (block-wide; ONE sync below) ----
#pragma unroll
    for (int t = 0; t < 16; ++t) {
        int idx = tid + t * 256;         // 0..4095 = k*64 + n
        int k = idx >> 6, n = idx & 63;
        sBl[n * BT_STRIDE + k] = Wl[idx];
        sBr[n * BT_STRIDE + k] = Wr[idx];
    }

    const float4* hin4 = (const float4*)hin;

    // ---- gather own 12 rows: half-warp per node, float4 lanes, unroll x4 ----
    for (int it = 0; it < 6; ++it) {
        int row = warp * 12 + it * 2 + half;
        int node = base + row;
        float4 m = make_float4(0.f, 0.f, 0.f, 0.f);
        if (node < N_NODES) {
            int start = g_rowptr[node], end = g_rowptr[node + 1];
            float4 a0 = make_float4(0.f, 0.f, 0.f, 0.f);
            float4 a1 = make_float4(0.f, 0.f, 0.f, 0.f);
            float4 a2 = make_float4(0.f, 0.f, 0.f, 0.f);
            float4 a3 = make_float4(0.f, 0.f, 0.f, 0.f);
            int e = start;
            for (; e + 3 < end; e += 4) {
                int s0 = g_csr[e],     s1 = g_csr[e + 1];
                int s2 = g_csr[e + 2], s3 = g_csr[e + 3];
                float4 v0 = hin4[s0 * 16 + hl];
                float4 v1 = hin4[s1 * 16 + hl];
                float4 v2 = hin4[s2 * 16 + hl];
                float4 v3 = hin4[s3 * 16 + hl];
                a0.x += v0.x; a0.y += v0.y; a0.z += v0.z; a0.w += v0.w;
                a1.x += v1.x; a1.y += v1.y; a1.z += v1.z; a1.w += v1.w;
                a2.x += v2.x; a2.y += v2.y; a2.z += v2.z; a2.w += v2.w;
                a3.x += v3.x; a3.y += v3.y; a3.z += v3.z; a3.w += v3.w;
            }
            for (; e < end; ++e) {
                int s0 = g_csr[e];
                float4 v0 = hin4[s0 * 16 + hl];
                a0.x += v0.x; a0.y += v0.y; a0.z += v0.z; a0.w += v0.w;
            }
            float inv = 1.0f / (float)max(end - start, 1);
            m.x = (a0.x + a1.x + a2.x + a3.x) * inv;
            m.y = (a0.y + a1.y + a2.y + a3.y) * inv;
            m.z = (a0.z + a1.z + a2.z + a3.z) * inv;
            m.w = (a0.w + a1.w + a2.w + a3.w) * inv;
        }
        *(float4*)&sA[row * A_STRIDE + hl * 4] = m;
    }
    __syncthreads();   // weights + all gather rows visible

    // ---- acc init: {bias, 0} pairs (lo = even-k sum + bias, hi = odd-k sum)
    unsigned long long acc2[6][4];
#pragma unroll
    for (int j = 0; j < 4; ++j) {
        unsigned long long bj = pack2(bias[tn + 16 * j], 0.0f);
#pragma unroll
        for (int i = 0; i < 6; ++i) acc2[i][j] = bj;
    }

    const int rowBase = tm * 6;

    // ---- GEMM1: acc += mean @ Wl (k-pair FFMA2) ----
#pragma unroll 4
    for (int k = 0; k < 64; k += 2) {
        unsigned long long b[4];
#pragma unroll
        for (int j = 0; j < 4; ++j)
            b[j] = *(const unsigned long long*)&sBl[(tn + 16 * j) * BT_STRIDE + k];
        unsigned long long a[6];
#pragma unroll
        for (int i = 0; i < 6; ++i)
            a[i] = *(const unsigned long long*)&sA[(rowBase + i) * A_STRIDE + k];
#pragma unroll
        for (int i = 0; i < 6; ++i)
#pragma unroll
            for (int j = 0; j < 4; ++j)
                fma2(acc2[i][j], a[i], b[j]);
    }
    __syncwarp();

    // ---- self-fill own 12 rows ----
#pragma unroll
    for (int t = 0; t < 6; ++t) {
        int idx = lane + t * 32;          // 0..191 over 12 rows x 16 col-groups
        int nl = idx >> 4, c = idx & 15;
        int row = warp * 12 + nl;
        int node = base + row;
        float4 v = make_float4(0.f, 0.f, 0.f, 0.f);
        if (node < N_NODES) v = hin4[node * 16 + c];
        *(float4*)&sA[row * A_STRIDE + c * 4] = v;
    }
    __syncwarp();

    // ---- GEMM2: acc += self @ Wr ----
#pragma unroll 4
    for (int k = 0; k < 64; k += 2) {
        unsigned long long b[4];
#pragma unroll
        for (int j = 0; j < 4; ++j)
            b[j] = *(const unsigned long long*)&sBr[(tn + 16 * j) * BT_STRIDE + k];
        unsigned long long a[6];
#pragma unroll
        for (int i = 0; i < 6; ++i)
            a[i] = *(const unsigned long long*)&sA[(rowBase + i) * A_STRIDE + k];
#pragma unroll
        for (int i = 0; i < 6; ++i)
#pragma unroll
            for (int j = 0; j < 4; ++j)
                fma2(acc2[i][j], a[i], b[j]);
    }

    // ---- epilogue: fold even/odd partial sums, relu, store ----
#pragma unroll
    for (int i = 0; i < 6; ++i) {
        int node = base + rowBase + i;
        if (node < N_NODES) {
#pragma unroll
            for (int j = 0; j < 4; ++j) {
                float2 p = unpack2(acc2[i][j]);
                float v = p.x + p.y;
                if (do_relu) v = fmaxf(v, 0.0f);
                hout[node * 64 + tn + 16 * j] = v;
            }
        }
    }
}

// ---------------- global add pool: g_h1 -> g_pool (batch is SORTED) -------
#define POOL_WARPS 784   // 98 blocks x 8 warps
__global__ void pool_kernel(const int* __restrict__ batch) {
    int w = blockIdx.x * 8 + (threadIdx.x >> 5);
    int lane = threadIdx.x & 31;
    const int chunk = (N_NODES + POOL_WARPS - 1) / POOL_WARPS;  // 128
    int start = w * chunk;
    int end = min(start + chunk, N_NODES);
    if (start >= end) return;

    const float2* h2 = (const float2*)g_h1;
    float2 acc = make_float2(0.f, 0.f);
    int cur_b = batch[start];
#pragma unroll 4
    for (int node = start; node < end; ++node) {
        int b = batch[node];
        if (b != cur_b) {
            atomicAdd(&g_pool[cur_b * 64 + 2 * lane],     acc.x);
            atomicAdd(&g_pool[cur_b * 64 + 2 * lane + 1], acc.y);
            acc = make_float2(0.f, 0.f);
            cur_b = b;
        }
        float2 v = h2[node * 32 + lane];
        acc.x += v.x; acc.y += v.y;
    }
    atomicAdd(&g_pool[cur_b * 64 + 2 * lane],     acc.x);
    atomicAdd(&g_pool[cur_b * 64 + 2 * lane + 1], acc.y);
}

// ---------------- MLP head: g_pool[256,64] -> out[256] ----------------
__global__ void mlp_kernel(const float* __restrict__ Wc1,
                           const float* __restrict__ bc1,
                           const float* __restrict__ Wc2,
                           const float* __restrict__ bc2,
                           float* __restrict__ out) {
    int gr = blockIdx.x * 8 + (threadIdx.x >> 5);
    int lane = threadIdx.x & 31;
    if (gr >= N_GRAPHS) return;
    float h = bc1[lane];
#pragma unroll
    for (int k = 0; k < 64; ++k)
        h += g_pool[gr * 64 + k] * Wc1[k * 32 + lane];
    h = fmaxf(h, 0.0f);
    float p = h * Wc2[lane];
#pragma unroll
    for (int off = 16; off > 0; off >>= 1)
        p += __shfl_xor_sync(0xffffffffu, p, off);
    if (lane == 0) out[gr] = p + bc2[0];
}

// ---------------- launch ----------------
extern "C" void kernel_launch(void* const* d_in, const int* in_sizes, int n_in,
                              void* d_out, int out_size) {
    const float* x     = (const float*)d_in[0];
    const int*   edge  = (const int*)d_in[1];     // int32 (JAX x64 disabled)
    const int*   batch = (const int*)d_in[2];     // int32
    const float* W1l = (const float*)d_in[3];
    const float* b1  = (const float*)d_in[4];
    const float* W1r = (const float*)d_in[5];
    const float* W2l = (const float*)d_in[6];
    const float* b2  = (const float*)d_in[7];
    const float* W2r = (const float*)d_in[8];
    const float* W3l = (const float*)d_in[9];
    const float* b3  = (const float*)d_in[10];
    const float* W3r = (const float*)d_in[11];
    const float* Wc1 = (const float*)d_in[12];
    const float* bc1 = (const float*)d_in[13];
    const float* Wc2 = (const float*)d_in[14];
    const float* bc2 = (const float*)d_in[15];
    float* out = (float*)d_out;

    cudaFuncSetAttribute(sage64_kernel,
                         cudaFuncAttributeMaxDynamicSharedMemorySize, SM64_BYTES);

    zero_kernel<<<(N_NODES + 255) / 256, 256>>>();
    count_kernel<<<(N_EDGES + 255) / 256, 256>>>(edge);
    scan_blocks_kernel<<<SCAN_BLOCKS, 1024>>>();
    scan_top_kernel<<<1, 128>>>();
    scan_add_kernel<<<SCAN_BLOCKS, 1024>>>();
    fill_kernel<<<(N_EDGES + 255) / 256, 256>>>(edge);

    const int NT8  = (N_NODES + 127) / 128;                // 782
    const int NT64 = (N_NODES + TILE_N64 - 1) / TILE_N64;  // 1042
    sage8_kernel<<<NT8, 256>>>(x, W1l, b1, W1r);
    sage64_kernel<<<NT64, 256, SM64_BYTES>>>(0, W2l, b2, W2r, 1);
    sage64_kernel<<<NT64, 256, SM64_BYTES>>>(1, W3l, b3, W3r, 0);

    pool_kernel<<<SCAN_BLOCKS, 256>>>(batch);
    mlp_kernel<<<32, 256>>>(Wc1, bc1, Wc2, bc2, out);
}

// round 11
// speedup vs baseline: 1.3310x; 1.3310x over previous
#include <cuda_runtime.h>
#include <cuda_bf16.h>

#define N_NODES  100000
#define N_EDGES  1200000
#define N_GRAPHS 256
#define SCAN_BLOCKS 98   // ceil(100000/1024)

// ---------------- device scratch (no allocs allowed) ----------------
// State contract per kernel_launch invocation: g_deg and g_pool are ZERO on
// entry (static init on first run; mlp_kernel re-zeroes them at the end of
// every run), so the captured graph replays deterministically.
__device__ int   g_deg[N_NODES];
__device__ int   g_rowptr[N_NODES + 1];
__device__ int   g_cur[N_NODES];
__device__ int   g_csr[N_EDGES];
__device__ int   g_bsums[SCAN_BLOCKS];
__device__ __align__(16) float g_h1[N_NODES * 64];
__device__ __align__(16) float g_h2[N_NODES * 64];
__device__ __align__(16) float g_pool[N_GRAPHS * 64];

// ---------------- CSR build ----------------
__global__ void count_kernel(const int* __restrict__ edge) {
    int e = blockIdx.x * blockDim.x + threadIdx.x;
    if (e < N_EDGES) {
        int dst = edge[N_EDGES + e];
        atomicAdd(&g_deg[dst], 1);
    }
}

__global__ void scan_blocks_kernel() {
    __shared__ int s[1024];
    int tid = threadIdx.x;
    int i = blockIdx.x * 1024 + tid;
    int v = (i < N_NODES) ? g_deg[i] : 0;
    s[tid] = v;
    __syncthreads();
    for (int off = 1; off < 1024; off <<= 1) {
        int t = (tid >= off) ? s[tid - off] : 0;
        __syncthreads();
        s[tid] += t;
        __syncthreads();
    }
    if (i < N_NODES) g_rowptr[i] = s[tid] - v;  // exclusive within block
    if (tid == 1023) g_bsums[blockIdx.x] = s[1023];
}

// fused top-level scan + add: every block recomputes the 98-entry prefix
__global__ void scan_fused_kernel() {
    __shared__ int s[128];
    int tid = threadIdx.x;
    if (tid < 128) s[tid] = (tid < SCAN_BLOCKS) ? g_bsums[tid] : 0;
    __syncthreads();
    for (int off = 1; off < 128; off <<= 1) {
        int t = (tid < 128 && tid >= off) ? s[tid - off] : 0;
        __syncthreads();
        if (tid < 128) s[tid] += t;
        __syncthreads();
    }
    int boff = (blockIdx.x == 0) ? 0 : s[blockIdx.x - 1];
    int i = blockIdx.x * 1024 + tid;
    if (i < N_NODES) {
        int r = g_rowptr[i] + boff;
        g_rowptr[i] = r;
        g_cur[i] = r;
    }
    if (i == 0) g_rowptr[N_NODES] = N_EDGES;
}

__global__ void fill_kernel(const int* __restrict__ edge) {
    int e = blockIdx.x * blockDim.x + threadIdx.x;
    if (e < N_EDGES) {
        int src = edge[e];
        int dst = edge[N_EDGES + e];
        int pos = atomicAdd(&g_cur[dst], 1);
        g_csr[pos] = src;
    }
}

// ---------------- layer 1: x[100k,8] -> g_h1[100k,64], relu ----------------
// 256 threads, 128 nodes. Gather uses ALL 8 warps: 2 lanes/node (p = lane&1
// picks float4 half), 16 nodes/warp, 1 LDG.128 per lane per edge.
#define A8_STRIDE 20   // 80 B rows: 16B-aligned for both p=0 and p=1 stores
__global__ void sage8_kernel(const float* __restrict__ x,
                             const float* __restrict__ Wl,
                             const float* __restrict__ bias,
                             const float* __restrict__ Wr) {
    __shared__ __align__(16) float sA[128 * A8_STRIDE]; // [node][16] mean|self
    __shared__ float sB[16 * 64];    // rows 0..7 = Wl, 8..15 = Wr
    __shared__ float sBias[64];

    const int tid = threadIdx.x;
    if (tid < 128) ((float4*)sB)[tid] = ((const float4*)Wl)[tid];
    else           ((float4*)sB)[tid] = ((const float4*)Wr)[tid - 128];
    if (tid < 64) sBias[tid] = bias[tid];

    const int base = blockIdx.x * 128;
    const float4* x4 = (const float4*)x;

    {
        const int lane = tid & 31;
        const int nodeLocal = (tid >> 5) * 16 + (lane >> 1);
        const int p = lane & 1;
        const int node = base + nodeLocal;
        float4 m  = make_float4(0.f, 0.f, 0.f, 0.f);
        float4 sf = make_float4(0.f, 0.f, 0.f, 0.f);
        if (node < N_NODES) {
            int start = g_rowptr[node], end = g_rowptr[node + 1];
            float4 a0 = make_float4(0.f, 0.f, 0.f, 0.f);
            float4 a1 = make_float4(0.f, 0.f, 0.f, 0.f);
            int e = start;
            for (; e + 1 < end; e += 2) {
                int s0 = g_csr[e], s1 = g_csr[e + 1];
                float4 v0 = x4[s0 * 2 + p];
                float4 v1 = x4[s1 * 2 + p];
                a0.x += v0.x; a0.y += v0.y; a0.z += v0.z; a0.w += v0.w;
                a1.x += v1.x; a1.y += v1.y; a1.z += v1.z; a1.w += v1.w;
            }
            if (e < end) {
                float4 v0 = x4[g_csr[e] * 2 + p];
                a0.x += v0.x; a0.y += v0.y; a0.z += v0.z; a0.w += v0.w;
            }
            float inv = 1.0f / (float)max(end - start, 1);
            m.x = (a0.x + a1.x) * inv; m.y = (a0.y + a1.y) * inv;
            m.z = (a0.z + a1.z) * inv; m.w = (a0.w + a1.w) * inv;
            sf = x4[node * 2 + p];
        }
        *(float4*)&sA[nodeLocal * A8_STRIDE + p * 4]     = m;   // mean cols
        *(float4*)&sA[nodeLocal * A8_STRIDE + 8 + p * 4] = sf;  // self cols
    }
    __syncthreads();

    const int tn = tid & 15, tm = tid >> 4;
    float acc[8][4];
#pragma unroll
    for (int i = 0; i < 8; ++i)
#pragma unroll
        for (int j = 0; j < 4; ++j) acc[i][j] = sBias[tn * 4 + j];

#pragma unroll
    for (int k = 0; k < 16; ++k) {
        float4 bv = *(const float4*)&sB[k * 64 + tn * 4];
        float a[8];
#pragma unroll
        for (int i = 0; i < 8; ++i) a[i] = sA[(tm * 8 + i) * A8_STRIDE + k];
#pragma unroll
        for (int i = 0; i < 8; ++i) {
            acc[i][0] += a[i] * bv.x;
            acc[i][1] += a[i] * bv.y;
            acc[i][2] += a[i] * bv.z;
            acc[i][3] += a[i] * bv.w;
        }
    }

    float4* hout4 = (float4*)g_h1;
#pragma unroll
    for (int i = 0; i < 8; ++i) {
        int node = base + tm * 8 + i;
        if (node < N_NODES) {
            float4 o;
            o.x = fmaxf(acc[i][0], 0.0f);
            o.y = fmaxf(acc[i][1], 0.0f);
            o.z = fmaxf(acc[i][2], 0.0f);
            o.w = fmaxf(acc[i][3], 0.0f);
            hout4[node * 16 + tn] = o;
        }
    }
}

// ---------------- layers 2/3: h[100k,64] -> h'[100k,64] (R8 structure) ----
// Warp-autonomous. Both weights resident; warp w owns rows [14w,14w+14).
// fuse_pool: layer 3 skips the h3 store and atomically accumulates per-graph
// sums into g_pool (batch is sorted -> ~1 run per thread).
#define TILE_N64 112
#define A_STRIDE 68   // 272 B rows, 16B-aligned
#define SM64_BYTES ((TILE_N64 * A_STRIDE + 2 * 4096) * 4)   // 63232

__global__ void __launch_bounds__(256) sage64_kernel(
                              int srcbuf,
                              const float* __restrict__ Wl,
                              const float* __restrict__ bias,
                              const float* __restrict__ Wr,
                              int do_relu, int fuse_pool,
                              const int* __restrict__ batch) {
    extern __shared__ float sm64[];
    float* sA  = sm64;                              // [112][68]
    float* sBl = sm64 + TILE_N64 * A_STRIDE;        // [64][64]
    float* sBr = sBl + 4096;                        // [64][64]

    const float* hin = (srcbuf == 0) ? g_h1 : g_h2;
    float* hout      = (srcbuf == 0) ? g_h2 : g_h1;

    const int tid  = threadIdx.x;
    const int base = blockIdx.x * TILE_N64;
    const int warp = tid >> 5, lane = tid & 31;
    const int lr = lane >> 4;        // 0/1: row half within warp's 14 rows
    const int hl = lane & 15;        // col group: cols [hl*4, hl*4+4)

    // ---- weights (only block-wide cooperation; ONE sync) ----
    {
        const float4* Wl4 = (const float4*)Wl;
        const float4* Wr4 = (const float4*)Wr;
        float4* l4 = (float4*)sBl;
        float4* r4 = (float4*)sBr;
#pragma unroll
        for (int t = 0; t < 4; ++t) {
            l4[tid + t * 256] = Wl4[tid + t * 256];
            r4[tid + t * 256] = Wr4[tid + t * 256];
        }
    }
    __syncthreads();

    const float4* hin4 = (const float4*)hin;
    const int rowBase = warp * 14 + lr * 7;

    // ---- gather own rows: half-warp per node, float4 lanes, unroll x4 ----
    for (int it = 0; it < 7; ++it) {
        int nodeLocal = rowBase + it;
        int node = base + nodeLocal;
        float4 m = make_float4(0.f, 0.f, 0.f, 0.f);
        if (node < N_NODES) {
            int start = g_rowptr[node], end = g_rowptr[node + 1];
            float4 a0 = make_float4(0.f, 0.f, 0.f, 0.f);
            float4 a1 = make_float4(0.f, 0.f, 0.f, 0.f);
            float4 a2 = make_float4(0.f, 0.f, 0.f, 0.f);
            float4 a3 = make_float4(0.f, 0.f, 0.f, 0.f);
            int e = start;
            for (; e + 3 < end; e += 4) {
                int s0 = g_csr[e],     s1 = g_csr[e + 1];
                int s2 = g_csr[e + 2], s3 = g_csr[e + 3];
                float4 v0 = hin4[s0 * 16 + hl];
                float4 v1 = hin4[s1 * 16 + hl];
                float4 v2 = hin4[s2 * 16 + hl];
                float4 v3 = hin4[s3 * 16 + hl];
                a0.x += v0.x; a0.y += v0.y; a0.z += v0.z; a0.w += v0.w;
                a1.x += v1.x; a1.y += v1.y; a1.z += v1.z; a1.w += v1.w;
                a2.x += v2.x; a2.y += v2.y; a2.z += v2.z; a2.w += v2.w;
                a3.x += v3.x; a3.y += v3.y; a3.z += v3.z; a3.w += v3.w;
            }
            for (; e < end; ++e) {
                int s0 = g_csr[e];
                float4 v0 = hin4[s0 * 16 + hl];
                a0.x += v0.x; a0.y += v0.y; a0.z += v0.z; a0.w += v0.w;
            }
            float inv = 1.0f / (float)max(end - start, 1);
            m.x = (a0.x + a1.x + a2.x + a3.x) * inv;
            m.y = (a0.y + a1.y + a2.y + a3.y) * inv;
            m.z = (a0.z + a1.z + a2.z + a3.z) * inv;
            m.w = (a0.w + a1.w + a2.w + a3.w) * inv;
        }
        *(float4*)&sA[nodeLocal * A_STRIDE + hl * 4] = m;
    }
    __syncwarp();

    // ---- acc init with bias ----
    float acc[7][4];
    {
        float4 bb = *(const float4*)&bias[hl * 4];
#pragma unroll
        for (int i = 0; i < 7; ++i) {
            acc[i][0] = bb.x; acc[i][1] = bb.y; acc[i][2] = bb.z; acc[i][3] = bb.w;
        }
    }

    // ---- GEMM1: acc += mean @ Wl (warp-local A rows) ----
#pragma unroll 4
    for (int k = 0; k < 64; k += 2) {
        float4 bv0 = *(const float4*)&sBl[k * 64 + hl * 4];
        float4 bv1 = *(const float4*)&sBl[(k + 1) * 64 + hl * 4];
        float2 a[7];
#pragma unroll
        for (int i = 0; i < 7; ++i)
            a[i] = *(const float2*)&sA[(rowBase + i) * A_STRIDE + k];
#pragma unroll
        for (int i = 0; i < 7; ++i) {
            acc[i][0] += a[i].x * bv0.x; acc[i][1] += a[i].x * bv0.y;
            acc[i][2] += a[i].x * bv0.z; acc[i][3] += a[i].x * bv0.w;
            acc[i][0] += a[i].y * bv1.x; acc[i][1] += a[i].y * bv1.y;
            acc[i][2] += a[i].y * bv1.z; acc[i][3] += a[i].y * bv1.w;
        }
    }
    __syncwarp();

    // ---- self-fill own 14 rows ----
#pragma unroll
    for (int t = 0; t < 7; ++t) {
        int idx = lane + t * 32;          // 0..223 over 14 rows x 16 cols
        int nl = idx >> 4, c = idx & 15;
        int nodeLocal = warp * 14 + nl;
        int node = base + nodeLocal;
        float4 v = make_float4(0.f, 0.f, 0.f, 0.f);
        if (node < N_NODES) v = hin4[node * 16 + c];
        *(float4*)&sA[nodeLocal * A_STRIDE + c * 4] = v;
    }
    __syncwarp();

    // ---- GEMM2: acc += self @ Wr ----
#pragma unroll 4
    for (int k = 0; k < 64; k += 2) {
        float4 bv0 = *(const float4*)&sBr[k * 64 + hl * 4];
        float4 bv1 = *(const float4*)&sBr[(k + 1) * 64 + hl * 4];
        float2 a[7];
#pragma unroll
        for (int i = 0; i < 7; ++i)
            a[i] = *(const float2*)&sA[(rowBase + i) * A_STRIDE + k];
#pragma unroll
        for (int i = 0; i < 7; ++i) {
            acc[i][0] += a[i].x * bv0.x; acc[i][1] += a[i].x * bv0.y;
            acc[i][2] += a[i].x * bv0.z; acc[i][3] += a[i].x * bv0.w;
            acc[i][0] += a[i].y * bv1.x; acc[i][1] += a[i].y * bv1.y;
            acc[i][2] += a[i].y * bv1.z; acc[i][3] += a[i].y * bv1.w;
        }
    }

    if (!fuse_pool) {
        // ---- store h' ----
        float4* hout4 = (float4*)hout;
#pragma unroll
        for (int i = 0; i < 7; ++i) {
            int node = base + rowBase + i;
            if (node < N_NODES) {
                float4 o;
                o.x = acc[i][0]; o.y = acc[i][1]; o.z = acc[i][2]; o.w = acc[i][3];
                if (do_relu) {
                    o.x = fmaxf(o.x, 0.f); o.y = fmaxf(o.y, 0.f);
                    o.z = fmaxf(o.z, 0.f); o.w = fmaxf(o.w, 0.f);
                }
                hout4[node * 16 + hl] = o;
            }
        }
    } else {
        // ---- layer 3: pool directly (batch sorted -> run-accumulate) ----
        int cur = -1;
        float4 s = make_float4(0.f, 0.f, 0.f, 0.f);
#pragma unroll
        for (int i = 0; i < 7; ++i) {
            int node = base + rowBase + i;
            if (node < N_NODES) {
                int b = batch[node];
                if (b != cur) {
                    if (cur >= 0) {
                        float* dst = &g_pool[cur * 64 + hl * 4];
                        atomicAdd(dst + 0, s.x);
                        atomicAdd(dst + 1, s.y);
                        atomicAdd(dst + 2, s.z);
                        atomicAdd(dst + 3, s.w);
                    }
                    cur = b;
                    s = make_float4(0.f, 0.f, 0.f, 0.f);
                }
                s.x += acc[i][0]; s.y += acc[i][1];
                s.z += acc[i][2]; s.w += acc[i][3];
            }
        }
        if (cur >= 0) {
            float* dst = &g_pool[cur * 64 + hl * 4];
            atomicAdd(dst + 0, s.x);
            atomicAdd(dst + 1, s.y);
            atomicAdd(dst + 2, s.z);
            atomicAdd(dst + 3, s.w);
        }
    }
}

// ---------------- MLP head + state re-zero for next replay ----------------
__global__ void mlp_kernel(const float* __restrict__ Wc1,
                           const float* __restrict__ bc1,
                           const float* __restrict__ Wc2,
                           const float* __restrict__ bc2,
                           float* __restrict__ out) {
    int gr = blockIdx.x * 8 + (threadIdx.x >> 5);
    int lane = threadIdx.x & 31;
    if (gr < N_GRAPHS) {
        float h = bc1[lane];
#pragma unroll
        for (int k = 0; k < 64; ++k)
            h += g_pool[gr * 64 + k] * Wc1[k * 32 + lane];
        h = fmaxf(h, 0.0f);
        float p = h * Wc2[lane];
#pragma unroll
        for (int off = 16; off > 0; off >>= 1)
            p += __shfl_xor_sync(0xffffffffu, p, off);
        if (lane == 0) out[gr] = p + bc2[0];
        // zero own pool row for next replay (reads above are complete)
        g_pool[gr * 64 + 2 * lane]     = 0.0f;
        g_pool[gr * 64 + 2 * lane + 1] = 0.0f;
    }
    // zero g_deg for next replay (grid-stride over 32x256 threads)
    int gtid = blockIdx.x * 256 + threadIdx.x;
    for (int i = gtid; i < N_NODES; i += 32 * 256) g_deg[i] = 0;
}

// ---------------- launch ----------------
extern "C" void kernel_launch(void* const* d_in, const int* in_sizes, int n_in,
                              void* d_out, int out_size) {
    const float* x     = (const float*)d_in[0];
    const int*   edge  = (const int*)d_in[1];     // int32 (JAX x64 disabled)
    const int*   batch = (const int*)d_in[2];     // int32
    const float* W1l = (const float*)d_in[3];
    const float* b1  = (const float*)d_in[4];
    const float* W1r = (const float*)d_in[5];
    const float* W2l = (const float*)d_in[6];
    const float* b2  = (const float*)d_in[7];
    const float* W2r = (const float*)d_in[8];
    const float* W3l = (const float*)d_in[9];
    const float* b3  = (const float*)d_in[10];
    const float* W3r = (const float*)d_in[11];
    const float* Wc1 = (const float*)d_in[12];
    const float* bc1 = (const float*)d_in[13];
    const float* Wc2 = (const float*)d_in[14];
    const float* bc2 = (const float*)d_in[15];
    float* out = (float*)d_out;

    cudaFuncSetAttribute(sage64_kernel,
                         cudaFuncAttributeMaxDynamicSharedMemorySize, SM64_BYTES);

    count_kernel<<<(N_EDGES + 255) / 256, 256>>>(edge);            // 1
    scan_blocks_kernel<<<SCAN_BLOCKS, 1024>>>();                   // 2
    scan_fused_kernel<<<SCAN_BLOCKS, 1024>>>();                    // 3
    fill_kernel<<<(N_EDGES + 255) / 256, 256>>>(edge);             // 4

    const int NT8  = (N_NODES + 127) / 128;                // 782
    const int NT64 = (N_NODES + TILE_N64 - 1) / TILE_N64;  // 893
    sage8_kernel<<<NT8, 256>>>(x, W1l, b1, W1r);                             // 5
    sage64_kernel<<<NT64, 256, SM64_BYTES>>>(0, W2l, b2, W2r, 1, 0, batch);  // 6
    sage64_kernel<<<NT64, 256, SM64_BYTES>>>(1, W3l, b3, W3r, 0, 1, batch);  // 7

    mlp_kernel<<<32, 256>>>(Wc1, bc1, Wc2, bc2, out);              // 8
}